// round 11
// baseline (speedup 1.0000x reference)
#include <cuda_runtime.h>
#include <math.h>
#include <stdint.h>

#define N_NODES 4096
#define N_EDGES 65536
#define N_BATCH 256
#define DEG_CTAS 16
#define FPSCALE 4096.0f            // 2^12 fixed-point scale (s16 range)
#define NCHUNKS 512                // node chunks of 8 (1 node per warp)
#define GPAIRS 4                   // 4 batch-groups x 64 batches = 256

// ---------------- scratch (no device allocations allowed) ----------------
__device__ int g_part_in[DEG_CTAS * N_NODES];
__device__ int g_part_out[DEG_CTAS * N_NODES];
__device__ int g_rowptr[N_NODES + 1];
__device__ int g_cursor[N_NODES];
__device__ unsigned short g_col[N_EDGES];
__device__ float g_csrcs[N_NODES];   // rsqrt(deg_out) * 2^12
__device__ float g_cdsts[N_NODES];   // rsqrt(deg_in)  * 2^-12
__device__ unsigned long long g_xqT[(size_t)N_NODES * N_BATCH];  // [node][batch] 3x s16
__device__ float g_partial[N_BATCH * NCHUNKS];

// packed f32x2 helpers
#define FMA_F32X2(out, a, b, c) \
    asm("fma.rn.f32x2 %0, %1, %2, %3;" : "=l"(out) : "l"(a), "l"(b), "l"(c))
__device__ __forceinline__ unsigned long long packf2(float lo, float hi) {
    unsigned long long r;
    asm("mov.b64 %0, {%1, %2};" : "=l"(r) : "f"(lo), "f"(hi));
    return r;
}
__device__ __forceinline__ void unpackf2(unsigned long long v, float& lo, float& hi) {
    asm("mov.b64 {%0, %1}, %2;" : "=f"(lo), "=f"(hi) : "l"(v));
}
__device__ __forceinline__ int q16(float v) {
    int f = __float2int_rn(v);
    f = max(-32768, min(32767, f));
    return f;
}

// -------- launch 0: per-CTA smem histogram of in/out degrees --------
__global__ __launch_bounds__(1024) void k_deg(const int* __restrict__ src,
                                              const int* __restrict__ dst) {
    __shared__ int sh_in[N_NODES];
    __shared__ int sh_out[N_NODES];
    int tid = threadIdx.x, cta = blockIdx.x;
    for (int i = tid; i < N_NODES; i += 1024) { sh_in[i] = 0; sh_out[i] = 0; }
    __syncthreads();
    int e0 = cta * (N_EDGES / DEG_CTAS);
    for (int i = tid; i < N_EDGES / DEG_CTAS; i += 1024) {
        atomicAdd(&sh_out[src[e0 + i]], 1);
        atomicAdd(&sh_in[dst[e0 + i]], 1);
    }
    __syncthreads();
    for (int i = tid; i < N_NODES; i += 1024) {
        g_part_in[cta * N_NODES + i] = sh_in[i];
        g_part_out[cta * N_NODES + i] = sh_out[i];
    }
}

// -------- launch 1: reduce partials, scan rowptr, norms, zero cursor --------
__global__ __launch_bounds__(1024) void k_scan() {
    __shared__ int ssum[1024];
    int t = threadIdx.x;
    int din[4], dout[4];
    #pragma unroll
    for (int j = 0; j < 4; j++) { din[j] = 0; dout[j] = 0; }
    #pragma unroll
    for (int c = 0; c < DEG_CTAS; c++) {
        #pragma unroll
        for (int j = 0; j < 4; j++) {
            din[j]  += g_part_in[c * N_NODES + 4 * t + j];
            dout[j] += g_part_out[c * N_NODES + 4 * t + j];
        }
    }
    int s = din[0] + din[1] + din[2] + din[3];
    ssum[t] = s;
    __syncthreads();
    for (int off = 1; off < 1024; off <<= 1) {
        int v = (t >= off) ? ssum[t - off] : 0;
        __syncthreads();
        ssum[t] += v;
        __syncthreads();
    }
    int excl = ssum[t] - s;
    g_rowptr[4 * t + 0] = excl;
    g_rowptr[4 * t + 1] = excl + din[0];
    g_rowptr[4 * t + 2] = excl + din[0] + din[1];
    g_rowptr[4 * t + 3] = excl + din[0] + din[1] + din[2];
    if (t == 1023) g_rowptr[N_NODES] = ssum[1023];
    #pragma unroll
    for (int j = 0; j < 4; j++) {
        int n = 4 * t + j;
        g_csrcs[n] = rsqrtf(fmaxf((float)dout[j], 1.0f)) * FPSCALE;
        g_cdsts[n] = rsqrtf(fmaxf((float)din[j], 1.0f)) * (1.0f / FPSCALE);
        g_cursor[n] = 0;
    }
}

// -------- launch 2: scatter edges into CSR (order-free: sums are integer) --------
__global__ __launch_bounds__(1024) void k_scatter(const int* __restrict__ src,
                                                  const int* __restrict__ dst) {
    int e = blockIdx.x * 1024 + threadIdx.x;
    if (e < N_EDGES) {
        int d = dst[e];
        int pos = atomicAdd(&g_cursor[d], 1);
        g_col[g_rowptr[d] + pos] = (unsigned short)src[e];
    }
}

// -------- launch 3: transpose+quantize x into [node][batch] u64 (3x s16) --------
// Tile = 32 nodes x 64 batches (25KB smem) -> 512 CTAs for occupancy.
__global__ __launch_bounds__(256) void k_stage(const float* __restrict__ x) {
    extern __shared__ float sx[];   // [64][97] padded (96 cols = 32 nodes * 3)
    int n0 = (blockIdx.x >> 2) * 32;
    int b0 = (blockIdx.x & 3) * 64;
    int tid = threadIdx.x;
    for (int i = tid; i < 64 * 96; i += 256) {
        int bl = i / 96, c = i - bl * 96;
        sx[bl * 97 + c] = x[(size_t)(b0 + bl) * (N_NODES * 3) + n0 * 3 + c];
    }
    __syncthreads();
    #pragma unroll
    for (int p = 0; p < 8; p++) {
        int idx = p * 256 + tid;
        int nl = idx >> 6, bl = idx & 63;
        int n = n0 + nl;
        float sc = g_csrcs[n];
        int f0 = q16(sx[bl * 97 + nl * 3 + 0] * sc);
        int f1 = q16(sx[bl * 97 + nl * 3 + 1] * sc);
        int f2 = q16(sx[bl * 97 + nl * 3 + 2] * sc);
        unsigned long long v = (unsigned long long)(unsigned short)f0
                             | ((unsigned long long)(unsigned short)f1 << 16)
                             | ((unsigned long long)(unsigned short)f2 << 32);
        g_xqT[(size_t)n * N_BATCH + b0 + bl] = v;
    }
}

// -------- launch 4: fused gather + MLP + fc partials --------
// Grid = 512 node-chunks x 4 batch-groups, CTA = 256 thr (8 warps),
// warp = ONE node x 64 batches; lane L carries batches gp*64+2L, +2L+1.
// Per edge: uniform neighbor index + ONE coalesced LDG.128 (512B/warp),
// int32 accumulation (deterministic). Then h = relu(y@W1+b1) via FFMA2
// col-pairs, acc += h.Wfc (uniform float2 LDG). CTA reduces 8 warps in
// fixed order -> g_partial[batch][chunk].
__global__ __launch_bounds__(256) void k_mainT(const float* __restrict__ W1,
                                               const float* __restrict__ b1,
                                               const float* __restrict__ Wfc) {
    __shared__ unsigned long long sw0[32], sw1[32], sw2[32], swb[32];
    __shared__ float red[8][64];
    int tid = threadIdx.x;
    int chunk = blockIdx.x >> 2;
    int gp = blockIdx.x & 3;
    if (tid < 32) {
        int j = 2 * tid;
        sw0[tid] = packf2(W1[j],        W1[j + 1]);
        sw1[tid] = packf2(W1[64 + j],   W1[64 + j + 1]);
        sw2[tid] = packf2(W1[128 + j],  W1[128 + j + 1]);
        swb[tid] = packf2(b1[j],        b1[j + 1]);
    }
    __syncthreads();
    int w = tid >> 5, L = tid & 31;
    int bA = gp * 64 + 2 * L;                 // lane's batch pair (bA, bA+1)
    const unsigned long long* xb = g_xqT + bA;

    int n = chunk * 8 + w;
    int k0 = g_rowptr[n], k1 = g_rowptr[n + 1];
    int aA0 = 0, aA1 = 0, aA2 = 0, aB0 = 0, aB1 = 0, aB2 = 0;
    #pragma unroll 4
    for (int k = k0; k < k1; k++) {
        int s = (int)g_col[k];
        ulonglong2 v = *(const ulonglong2*)(xb + (size_t)s * N_BATCH);
        aA0 += (int)(short)v.x;
        aA1 += (int)(short)(v.x >> 16);
        aA2 += (int)(short)(v.x >> 32);
        aB0 += (int)(short)v.y;
        aB1 += (int)(short)(v.y >> 16);
        aB2 += (int)(short)(v.y >> 32);
    }
    float cd = g_cdsts[n];
    float yA0 = aA0 * cd, yA1 = aA1 * cd, yA2 = aA2 * cd;
    float yB0 = aB0 * cd, yB1 = aB1 * cd, yB2 = aB2 * cd;
    unsigned long long pA0 = packf2(yA0, yA0), pA1 = packf2(yA1, yA1), pA2 = packf2(yA2, yA2);
    unsigned long long pB0 = packf2(yB0, yB0), pB1 = packf2(yB1, yB1), pB2 = packf2(yB2, yB2);

    float accA = 0.f, accB = 0.f;
    const float2* wfr = (const float2*)(Wfc + n * 64);
    #pragma unroll 8
    for (int j = 0; j < 32; j++) {
        float2 wf = wfr[j];                   // uniform LDG.64 (broadcast)
        unsigned long long hA, hB;
        FMA_F32X2(hA, pA0, sw0[j], swb[j]);
        FMA_F32X2(hA, pA1, sw1[j], hA);
        FMA_F32X2(hA, pA2, sw2[j], hA);
        FMA_F32X2(hB, pB0, sw0[j], swb[j]);
        FMA_F32X2(hB, pB1, sw1[j], hB);
        FMA_F32X2(hB, pB2, sw2[j], hB);
        float a0, a1, c0, c1;
        unpackf2(hA, a0, a1);
        unpackf2(hB, c0, c1);
        accA = fmaf(fmaxf(a0, 0.f), wf.x, accA);
        accA = fmaf(fmaxf(a1, 0.f), wf.y, accA);
        accB = fmaf(fmaxf(c0, 0.f), wf.x, accB);
        accB = fmaf(fmaxf(c1, 0.f), wf.y, accB);
    }
    red[w][2 * L]     = accA;
    red[w][2 * L + 1] = accB;
    __syncthreads();
    if (tid < 64) {
        float s = 0.f;
        #pragma unroll
        for (int ww = 0; ww < 8; ww++) s += red[ww][tid];   // fixed order
        g_partial[(gp * 64 + tid) * NCHUNKS + chunk] = s;
    }
}

// -------- launch 5: reduce 512 chunk-partials per batch, sigmoid --------
__global__ __launch_bounds__(1024) void k_final(const float* __restrict__ bfc,
                                                float* __restrict__ out) {
    int b = blockIdx.x * 32 + (threadIdx.x >> 5);
    int L = threadIdx.x & 31;
    float s = 0.f;
    #pragma unroll
    for (int i = 0; i < 16; i++) s += g_partial[b * NCHUNKS + L + 32 * i];
    #pragma unroll
    for (int off = 16; off; off >>= 1) s += __shfl_xor_sync(0xffffffffu, s, off);
    if (L == 0) out[b] = 1.0f / (1.0f + expf(-(s + bfc[0])));
}

// ---------------- launch ----------------
extern "C" void kernel_launch(void* const* d_in, const int* in_sizes, int n_in,
                              void* d_out, int out_size) {
    const float* x   = (const float*)d_in[0];
    const float* W1  = (const float*)d_in[1];
    const float* b1  = (const float*)d_in[2];
    const float* Wfc = (const float*)d_in[3];
    const float* bfc = (const float*)d_in[4];
    const int*   src = (const int*)d_in[5];
    const int*   dst = (const int*)d_in[6];
    float* out = (float*)d_out;

    const int stage_smem = 64 * 97 * 4;   // 24832 B
    cudaFuncSetAttribute(k_stage, cudaFuncAttributeMaxDynamicSharedMemorySize, stage_smem);

    k_deg<<<DEG_CTAS, 1024>>>(src, dst);
    k_scan<<<1, 1024>>>();
    k_scatter<<<N_EDGES / 1024, 1024>>>(src, dst);
    k_stage<<<512, 256, stage_smem>>>(x);
    k_mainT<<<NCHUNKS * GPAIRS, 256>>>(W1, b1, Wfc);
    k_final<<<8, 1024>>>(bfc, out);
}

// round 12
// speedup vs baseline: 1.4935x; 1.4935x over previous
#include <cuda_runtime.h>
#include <math.h>
#include <stdint.h>

#define N_NODES 4096
#define N_EDGES 65536
#define N_BATCH 256
#define DEG_CTAS 16
#define FPSCALE 4096.0f            // 2^12 fixed-point scale (s16 range)
#define NCHUNKS 512                // node chunks of 8 (1 node per warp)
#define GPAIRS 4                   // 4 batch-groups x 64 batches = 256

// ---------------- scratch (no device allocations allowed) ----------------
__device__ int g_part_in[DEG_CTAS * N_NODES];
__device__ int g_part_out[DEG_CTAS * N_NODES];
__device__ int g_rowptr[N_NODES + 1];
__device__ int g_cursor[N_NODES];
__device__ unsigned short g_col[N_EDGES];
__device__ float g_csrcs[N_NODES];   // rsqrt(deg_out) * 2^12
__device__ float g_cdsts[N_NODES];   // rsqrt(deg_in)  * 2^-12
__device__ unsigned long long g_xqT[(size_t)N_NODES * N_BATCH];  // [node][batch] 3x s16
__device__ float g_partial[N_BATCH * NCHUNKS];

// packed f32x2 helpers
#define FMA_F32X2(out, a, b, c) \
    asm("fma.rn.f32x2 %0, %1, %2, %3;" : "=l"(out) : "l"(a), "l"(b), "l"(c))
__device__ __forceinline__ unsigned long long packf2(float lo, float hi) {
    unsigned long long r;
    asm("mov.b64 %0, {%1, %2};" : "=l"(r) : "f"(lo), "f"(hi));
    return r;
}
__device__ __forceinline__ void unpackf2(unsigned long long v, float& lo, float& hi) {
    asm("mov.b64 {%0, %1}, %2;" : "=f"(lo), "=f"(hi) : "l"(v));
}
__device__ __forceinline__ int q16(float v) {
    int f = __float2int_rn(v);
    f = max(-32768, min(32767, f));
    return f;
}

// -------- launch 0: per-CTA smem histogram of in/out degrees --------
__global__ __launch_bounds__(1024) void k_deg(const int* __restrict__ src,
                                              const int* __restrict__ dst) {
    __shared__ int sh_in[N_NODES];
    __shared__ int sh_out[N_NODES];
    int tid = threadIdx.x, cta = blockIdx.x;
    for (int i = tid; i < N_NODES; i += 1024) { sh_in[i] = 0; sh_out[i] = 0; }
    __syncthreads();
    int e0 = cta * (N_EDGES / DEG_CTAS);
    for (int i = tid; i < N_EDGES / DEG_CTAS; i += 1024) {
        atomicAdd(&sh_out[src[e0 + i]], 1);
        atomicAdd(&sh_in[dst[e0 + i]], 1);
    }
    __syncthreads();
    for (int i = tid; i < N_NODES; i += 1024) {
        g_part_in[cta * N_NODES + i] = sh_in[i];
        g_part_out[cta * N_NODES + i] = sh_out[i];
    }
}

// -------- launch 1: reduce partials, scan rowptr, norms, zero cursor --------
__global__ __launch_bounds__(1024) void k_scan() {
    __shared__ int ssum[1024];
    int t = threadIdx.x;
    int din[4], dout[4];
    #pragma unroll
    for (int j = 0; j < 4; j++) { din[j] = 0; dout[j] = 0; }
    #pragma unroll
    for (int c = 0; c < DEG_CTAS; c++) {
        #pragma unroll
        for (int j = 0; j < 4; j++) {
            din[j]  += g_part_in[c * N_NODES + 4 * t + j];
            dout[j] += g_part_out[c * N_NODES + 4 * t + j];
        }
    }
    int s = din[0] + din[1] + din[2] + din[3];
    ssum[t] = s;
    __syncthreads();
    for (int off = 1; off < 1024; off <<= 1) {
        int v = (t >= off) ? ssum[t - off] : 0;
        __syncthreads();
        ssum[t] += v;
        __syncthreads();
    }
    int excl = ssum[t] - s;
    g_rowptr[4 * t + 0] = excl;
    g_rowptr[4 * t + 1] = excl + din[0];
    g_rowptr[4 * t + 2] = excl + din[0] + din[1];
    g_rowptr[4 * t + 3] = excl + din[0] + din[1] + din[2];
    if (t == 1023) g_rowptr[N_NODES] = ssum[1023];
    #pragma unroll
    for (int j = 0; j < 4; j++) {
        int n = 4 * t + j;
        g_csrcs[n] = rsqrtf(fmaxf((float)dout[j], 1.0f)) * FPSCALE;
        g_cdsts[n] = rsqrtf(fmaxf((float)din[j], 1.0f)) * (1.0f / FPSCALE);
        g_cursor[n] = 0;
    }
}

// -------- launch 2: scatter edges into CSR (order-free: sums are integer) --------
__global__ __launch_bounds__(1024) void k_scatter(const int* __restrict__ src,
                                                  const int* __restrict__ dst) {
    int e = blockIdx.x * 1024 + threadIdx.x;
    if (e < N_EDGES) {
        int d = dst[e];
        int pos = atomicAdd(&g_cursor[d], 1);
        g_col[g_rowptr[d] + pos] = (unsigned short)src[e];
    }
}

// -------- launch 3: transpose+quantize x into [node][batch] u64 (3x s16) --------
// Tile = 32 nodes x 64 batches (25KB smem) -> 512 CTAs for occupancy.
__global__ __launch_bounds__(256) void k_stage(const float* __restrict__ x) {
    extern __shared__ float sx[];   // [64][97] padded (96 cols = 32 nodes * 3)
    int n0 = (blockIdx.x >> 2) * 32;
    int b0 = (blockIdx.x & 3) * 64;
    int tid = threadIdx.x;
    for (int i = tid; i < 64 * 96; i += 256) {
        int bl = i / 96, c = i - bl * 96;
        sx[bl * 97 + c] = x[(size_t)(b0 + bl) * (N_NODES * 3) + n0 * 3 + c];
    }
    __syncthreads();
    #pragma unroll
    for (int p = 0; p < 8; p++) {
        int idx = p * 256 + tid;
        int nl = idx >> 6, bl = idx & 63;
        int n = n0 + nl;
        float sc = g_csrcs[n];
        int f0 = q16(sx[bl * 97 + nl * 3 + 0] * sc);
        int f1 = q16(sx[bl * 97 + nl * 3 + 1] * sc);
        int f2 = q16(sx[bl * 97 + nl * 3 + 2] * sc);
        unsigned long long v = (unsigned long long)(unsigned short)f0
                             | ((unsigned long long)(unsigned short)f1 << 16)
                             | ((unsigned long long)(unsigned short)f2 << 32);
        g_xqT[(size_t)n * N_BATCH + b0 + bl] = v;
    }
}

// -------- launch 4: fused gather + MLP + fc partials --------
// Grid = 512 node-chunks x 4 batch-groups, CTA = 256 thr (8 warps),
// warp = ONE node x 64 batches; lane L carries batches gp*64+2L, +2L+1.
// Per edge: uniform neighbor index + ONE coalesced LDG.128 (512B/warp),
// int32 accumulation (deterministic). Then h = relu(y@W1+b1) via FFMA2
// col-pairs, acc += h.Wfc (uniform float2 LDG). CTA reduces 8 warps in
// fixed order -> g_partial[batch][chunk].
__global__ __launch_bounds__(256) void k_mainT(const float* __restrict__ W1,
                                               const float* __restrict__ b1,
                                               const float* __restrict__ Wfc) {
    __shared__ unsigned long long sw0[32], sw1[32], sw2[32], swb[32];
    __shared__ float red[8][64];
    int tid = threadIdx.x;
    int chunk = blockIdx.x >> 2;
    int gp = blockIdx.x & 3;
    if (tid < 32) {
        int j = 2 * tid;
        sw0[tid] = packf2(W1[j],        W1[j + 1]);
        sw1[tid] = packf2(W1[64 + j],   W1[64 + j + 1]);
        sw2[tid] = packf2(W1[128 + j],  W1[128 + j + 1]);
        swb[tid] = packf2(b1[j],        b1[j + 1]);
    }
    __syncthreads();
    int w = tid >> 5, L = tid & 31;
    int bA = gp * 64 + 2 * L;                 // lane's batch pair (bA, bA+1)
    const unsigned long long* xb = g_xqT + bA;

    int n = chunk * 8 + w;
    int k0 = g_rowptr[n], k1 = g_rowptr[n + 1];
    int aA0 = 0, aA1 = 0, aA2 = 0, aB0 = 0, aB1 = 0, aB2 = 0;
    #pragma unroll 4
    for (int k = k0; k < k1; k++) {
        int s = (int)g_col[k];
        ulonglong2 v = *(const ulonglong2*)(xb + (size_t)s * N_BATCH);
        aA0 += (int)(short)v.x;
        aA1 += (int)(short)(v.x >> 16);
        aA2 += (int)(short)(v.x >> 32);
        aB0 += (int)(short)v.y;
        aB1 += (int)(short)(v.y >> 16);
        aB2 += (int)(short)(v.y >> 32);
    }
    float cd = g_cdsts[n];
    float yA0 = aA0 * cd, yA1 = aA1 * cd, yA2 = aA2 * cd;
    float yB0 = aB0 * cd, yB1 = aB1 * cd, yB2 = aB2 * cd;
    unsigned long long pA0 = packf2(yA0, yA0), pA1 = packf2(yA1, yA1), pA2 = packf2(yA2, yA2);
    unsigned long long pB0 = packf2(yB0, yB0), pB1 = packf2(yB1, yB1), pB2 = packf2(yB2, yB2);

    float accA = 0.f, accB = 0.f;
    const float2* wfr = (const float2*)(Wfc + n * 64);
    #pragma unroll 8
    for (int j = 0; j < 32; j++) {
        float2 wf = wfr[j];                   // uniform LDG.64 (broadcast)
        unsigned long long hA, hB;
        FMA_F32X2(hA, pA0, sw0[j], swb[j]);
        FMA_F32X2(hA, pA1, sw1[j], hA);
        FMA_F32X2(hA, pA2, sw2[j], hA);
        FMA_F32X2(hB, pB0, sw0[j], swb[j]);
        FMA_F32X2(hB, pB1, sw1[j], hB);
        FMA_F32X2(hB, pB2, sw2[j], hB);
        float a0, a1, c0, c1;
        unpackf2(hA, a0, a1);
        unpackf2(hB, c0, c1);
        accA = fmaf(fmaxf(a0, 0.f), wf.x, accA);
        accA = fmaf(fmaxf(a1, 0.f), wf.y, accA);
        accB = fmaf(fmaxf(c0, 0.f), wf.x, accB);
        accB = fmaf(fmaxf(c1, 0.f), wf.y, accB);
    }
    red[w][2 * L]     = accA;
    red[w][2 * L + 1] = accB;
    __syncthreads();
    if (tid < 64) {
        float s = 0.f;
        #pragma unroll
        for (int ww = 0; ww < 8; ww++) s += red[ww][tid];   // fixed order
        g_partial[(gp * 64 + tid) * NCHUNKS + chunk] = s;
    }
}

// -------- launch 5: reduce 512 chunk-partials per batch, sigmoid --------
__global__ __launch_bounds__(1024) void k_final(const float* __restrict__ bfc,
                                                float* __restrict__ out) {
    int b = blockIdx.x * 32 + (threadIdx.x >> 5);
    int L = threadIdx.x & 31;
    float s = 0.f;
    #pragma unroll
    for (int i = 0; i < 16; i++) s += g_partial[b * NCHUNKS + L + 32 * i];
    #pragma unroll
    for (int off = 16; off; off >>= 1) s += __shfl_xor_sync(0xffffffffu, s, off);
    if (L == 0) out[b] = 1.0f / (1.0f + expf(-(s + bfc[0])));
}

// ---------------- launch ----------------
extern "C" void kernel_launch(void* const* d_in, const int* in_sizes, int n_in,
                              void* d_out, int out_size) {
    const float* x   = (const float*)d_in[0];
    const float* W1  = (const float*)d_in[1];
    const float* b1  = (const float*)d_in[2];
    const float* Wfc = (const float*)d_in[3];
    const float* bfc = (const float*)d_in[4];
    const int*   src = (const int*)d_in[5];
    const int*   dst = (const int*)d_in[6];
    float* out = (float*)d_out;

    const int stage_smem = 64 * 97 * 4;   // 24832 B
    cudaFuncSetAttribute(k_stage, cudaFuncAttributeMaxDynamicSharedMemorySize, stage_smem);

    k_deg<<<DEG_CTAS, 1024>>>(src, dst);
    k_scan<<<1, 1024>>>();
    k_scatter<<<N_EDGES / 1024, 1024>>>(src, dst);
    k_stage<<<512, 256, stage_smem>>>(x);
    k_mainT<<<NCHUNKS * GPAIRS, 256>>>(W1, b1, Wfc);
    k_final<<<8, 1024>>>(bfc, out);
}

// round 14
// speedup vs baseline: 1.5123x; 1.0126x over previous
#include <cuda_runtime.h>
#include <math.h>
#include <stdint.h>

#define N_NODES 4096
#define N_EDGES 65536
#define N_BATCH 256
#define DEG_CTAS 16
#define FPSCALE 4096.0f            // 2^12 fixed-point scale (s16 range)
#define NCHUNKS 512                // node chunks of 8 (1 node per warp)
#define GPAIRS 4                   // 4 batch-groups x 64 batches = 256

// ---------------- scratch (no device allocations allowed) ----------------
__device__ int g_part_in[DEG_CTAS * N_NODES];
__device__ int g_part_out[DEG_CTAS * N_NODES];
__device__ int g_rowptr[N_NODES + 1];
__device__ int g_cursor[N_NODES];
__device__ unsigned short g_col[N_EDGES];
__device__ float g_csrcs[N_NODES];   // rsqrt(deg_out) * 2^12
__device__ float g_cdsts[N_NODES];   // rsqrt(deg_in)  * 2^-12
__device__ unsigned long long g_xqT[(size_t)N_NODES * N_BATCH];  // [node][batch] 3x s16
__device__ float g_partial[N_BATCH * NCHUNKS];

// packed f32x2 helpers
#define FMA_F32X2(out, a, b, c) \
    asm("fma.rn.f32x2 %0, %1, %2, %3;" : "=l"(out) : "l"(a), "l"(b), "l"(c))
__device__ __forceinline__ unsigned long long packf2(float lo, float hi) {
    unsigned long long r;
    asm("mov.b64 %0, {%1, %2};" : "=l"(r) : "f"(lo), "f"(hi));
    return r;
}
__device__ __forceinline__ void unpackf2(unsigned long long v, float& lo, float& hi) {
    asm("mov.b64 {%0, %1}, %2;" : "=f"(lo), "=f"(hi) : "l"(v));
}
__device__ __forceinline__ int q16(float v) {
    int f = __float2int_rn(v);
    f = max(-32768, min(32767, f));
    return f;
}

// -------- launch 0: per-CTA smem histogram of in/out degrees --------
__global__ __launch_bounds__(1024) void k_deg(const int* __restrict__ src,
                                              const int* __restrict__ dst) {
    __shared__ int sh_in[N_NODES];
    __shared__ int sh_out[N_NODES];
    int tid = threadIdx.x, cta = blockIdx.x;
    for (int i = tid; i < N_NODES; i += 1024) { sh_in[i] = 0; sh_out[i] = 0; }
    __syncthreads();
    int e0 = cta * (N_EDGES / DEG_CTAS);
    for (int i = tid; i < N_EDGES / DEG_CTAS; i += 1024) {
        atomicAdd(&sh_out[src[e0 + i]], 1);
        atomicAdd(&sh_in[dst[e0 + i]], 1);
    }
    __syncthreads();
    for (int i = tid; i < N_NODES; i += 1024) {
        g_part_in[cta * N_NODES + i] = sh_in[i];
        g_part_out[cta * N_NODES + i] = sh_out[i];
    }
}

// -------- launch 1: reduce partials, scan rowptr, norms, zero cursor --------
__global__ __launch_bounds__(1024) void k_scan() {
    __shared__ int ssum[1024];
    int t = threadIdx.x;
    int din[4], dout[4];
    #pragma unroll
    for (int j = 0; j < 4; j++) { din[j] = 0; dout[j] = 0; }
    #pragma unroll
    for (int c = 0; c < DEG_CTAS; c++) {
        #pragma unroll
        for (int j = 0; j < 4; j++) {
            din[j]  += g_part_in[c * N_NODES + 4 * t + j];
            dout[j] += g_part_out[c * N_NODES + 4 * t + j];
        }
    }
    int s = din[0] + din[1] + din[2] + din[3];
    ssum[t] = s;
    __syncthreads();
    for (int off = 1; off < 1024; off <<= 1) {
        int v = (t >= off) ? ssum[t - off] : 0;
        __syncthreads();
        ssum[t] += v;
        __syncthreads();
    }
    int excl = ssum[t] - s;
    g_rowptr[4 * t + 0] = excl;
    g_rowptr[4 * t + 1] = excl + din[0];
    g_rowptr[4 * t + 2] = excl + din[0] + din[1];
    g_rowptr[4 * t + 3] = excl + din[0] + din[1] + din[2];
    if (t == 1023) g_rowptr[N_NODES] = ssum[1023];
    #pragma unroll
    for (int j = 0; j < 4; j++) {
        int n = 4 * t + j;
        g_csrcs[n] = rsqrtf(fmaxf((float)dout[j], 1.0f)) * FPSCALE;
        g_cdsts[n] = rsqrtf(fmaxf((float)din[j], 1.0f)) * (1.0f / FPSCALE);
        g_cursor[n] = 0;
    }
}

// -------- launch 2: scatter edges into CSR (order-free: sums are integer) --------
__global__ __launch_bounds__(1024) void k_scatter(const int* __restrict__ src,
                                                  const int* __restrict__ dst) {
    int e = blockIdx.x * 1024 + threadIdx.x;
    if (e < N_EDGES) {
        int d = dst[e];
        int pos = atomicAdd(&g_cursor[d], 1);
        g_col[g_rowptr[d] + pos] = (unsigned short)src[e];
    }
}

// -------- launch 3: transpose+quantize x into [node][batch] u64 (3x s16) --------
// Tile = 32 nodes x 64 batches (25KB smem) -> 512 CTAs for occupancy.
__global__ __launch_bounds__(256) void k_stage(const float* __restrict__ x) {
    extern __shared__ float sx[];   // [64][97] padded (96 cols = 32 nodes * 3)
    int n0 = (blockIdx.x >> 2) * 32;
    int b0 = (blockIdx.x & 3) * 64;
    int tid = threadIdx.x;
    for (int i = tid; i < 64 * 96; i += 256) {
        int bl = i / 96, c = i - bl * 96;
        sx[bl * 97 + c] = x[(size_t)(b0 + bl) * (N_NODES * 3) + n0 * 3 + c];
    }
    __syncthreads();
    #pragma unroll
    for (int p = 0; p < 8; p++) {
        int idx = p * 256 + tid;
        int nl = idx >> 6, bl = idx & 63;
        int n = n0 + nl;
        float sc = g_csrcs[n];
        int f0 = q16(sx[bl * 97 + nl * 3 + 0] * sc);
        int f1 = q16(sx[bl * 97 + nl * 3 + 1] * sc);
        int f2 = q16(sx[bl * 97 + nl * 3 + 2] * sc);
        unsigned long long v = (unsigned long long)(unsigned short)f0
                             | ((unsigned long long)(unsigned short)f1 << 16)
                             | ((unsigned long long)(unsigned short)f2 << 32);
        g_xqT[(size_t)n * N_BATCH + b0 + bl] = v;
    }
}

// -------- launch 4: fused gather + MLP + fc partials --------
// Grid = 512 node-chunks x 4 batch-groups, CTA = 256 thr (8 warps),
// warp = ONE node x 64 batches; lane L carries batches gp*64+2L, +2L+1.
// Per edge: uniform neighbor index + ONE coalesced LDG.128 (512B/warp),
// int32 accumulation (deterministic). Then h = relu(y@W1+b1) via FFMA2
// col-pairs, acc += h.Wfc (uniform float2 LDG). CTA reduces 8 warps in
// fixed order -> g_partial[batch][chunk].
__global__ __launch_bounds__(256) void k_mainT(const float* __restrict__ W1,
                                               const float* __restrict__ b1,
                                               const float* __restrict__ Wfc) {
    __shared__ unsigned long long sw0[32], sw1[32], sw2[32], swb[32];
    __shared__ float red[8][64];
    int tid = threadIdx.x;
    int chunk = blockIdx.x >> 2;
    int gp = blockIdx.x & 3;
    if (tid < 32) {
        int j = 2 * tid;
        sw0[tid] = packf2(W1[j],        W1[j + 1]);
        sw1[tid] = packf2(W1[64 + j],   W1[64 + j + 1]);
        sw2[tid] = packf2(W1[128 + j],  W1[128 + j + 1]);
        swb[tid] = packf2(b1[j],        b1[j + 1]);
    }
    __syncthreads();
    int w = tid >> 5, L = tid & 31;
    int bA = gp * 64 + 2 * L;                 // lane's batch pair (bA, bA+1)
    const unsigned long long* xb = g_xqT + bA;

    int n = chunk * 8 + w;
    int k0 = g_rowptr[n], k1 = g_rowptr[n + 1];
    int aA0 = 0, aA1 = 0, aA2 = 0, aB0 = 0, aB1 = 0, aB2 = 0;
    #pragma unroll 4
    for (int k = k0; k < k1; k++) {
        int s = (int)g_col[k];
        ulonglong2 v = *(const ulonglong2*)(xb + (size_t)s * N_BATCH);
        aA0 += (int)(short)v.x;
        aA1 += (int)(short)(v.x >> 16);
        aA2 += (int)(short)(v.x >> 32);
        aB0 += (int)(short)v.y;
        aB1 += (int)(short)(v.y >> 16);
        aB2 += (int)(short)(v.y >> 32);
    }
    float cd = g_cdsts[n];
    float yA0 = aA0 * cd, yA1 = aA1 * cd, yA2 = aA2 * cd;
    float yB0 = aB0 * cd, yB1 = aB1 * cd, yB2 = aB2 * cd;
    unsigned long long pA0 = packf2(yA0, yA0), pA1 = packf2(yA1, yA1), pA2 = packf2(yA2, yA2);
    unsigned long long pB0 = packf2(yB0, yB0), pB1 = packf2(yB1, yB1), pB2 = packf2(yB2, yB2);

    float accA = 0.f, accB = 0.f;
    const float2* wfr = (const float2*)(Wfc + n * 64);
    #pragma unroll 8
    for (int j = 0; j < 32; j++) {
        float2 wf = wfr[j];                   // uniform LDG.64 (broadcast)
        unsigned long long hA, hB;
        FMA_F32X2(hA, pA0, sw0[j], swb[j]);
        FMA_F32X2(hA, pA1, sw1[j], hA);
        FMA_F32X2(hA, pA2, sw2[j], hA);
        FMA_F32X2(hB, pB0, sw0[j], swb[j]);
        FMA_F32X2(hB, pB1, sw1[j], hB);
        FMA_F32X2(hB, pB2, sw2[j], hB);
        float a0, a1, c0, c1;
        unpackf2(hA, a0, a1);
        unpackf2(hB, c0, c1);
        accA = fmaf(fmaxf(a0, 0.f), wf.x, accA);
        accA = fmaf(fmaxf(a1, 0.f), wf.y, accA);
        accB = fmaf(fmaxf(c0, 0.f), wf.x, accB);
        accB = fmaf(fmaxf(c1, 0.f), wf.y, accB);
    }
    red[w][2 * L]     = accA;
    red[w][2 * L + 1] = accB;
    __syncthreads();
    if (tid < 64) {
        float s = 0.f;
        #pragma unroll
        for (int ww = 0; ww < 8; ww++) s += red[ww][tid];   // fixed order
        g_partial[(gp * 64 + tid) * NCHUNKS + chunk] = s;
    }
}

// -------- launch 5: reduce 512 chunk-partials per batch, sigmoid --------
__global__ __launch_bounds__(1024) void k_final(const float* __restrict__ bfc,
                                                float* __restrict__ out) {
    int b = blockIdx.x * 32 + (threadIdx.x >> 5);
    int L = threadIdx.x & 31;
    float s = 0.f;
    #pragma unroll
    for (int i = 0; i < 16; i++) s += g_partial[b * NCHUNKS + L + 32 * i];
    #pragma unroll
    for (int off = 16; off; off >>= 1) s += __shfl_xor_sync(0xffffffffu, s, off);
    if (L == 0) out[b] = 1.0f / (1.0f + expf(-(s + bfc[0])));
}

// ---------------- launch ----------------
extern "C" void kernel_launch(void* const* d_in, const int* in_sizes, int n_in,
                              void* d_out, int out_size) {
    const float* x   = (const float*)d_in[0];
    const float* W1  = (const float*)d_in[1];
    const float* b1  = (const float*)d_in[2];
    const float* Wfc = (const float*)d_in[3];
    const float* bfc = (const float*)d_in[4];
    const int*   src = (const int*)d_in[5];
    const int*   dst = (const int*)d_in[6];
    float* out = (float*)d_out;

    const int stage_smem = 64 * 97 * 4;   // 24832 B
    cudaFuncSetAttribute(k_stage, cudaFuncAttributeMaxDynamicSharedMemorySize, stage_smem);

    k_deg<<<DEG_CTAS, 1024>>>(src, dst);
    k_scan<<<1, 1024>>>();
    k_scatter<<<N_EDGES / 1024, 1024>>>(src, dst);
    k_stage<<<512, 256, stage_smem>>>(x);
    k_mainT<<<NCHUNKS * GPAIRS, 256>>>(W1, b1, Wfc);
    k_final<<<8, 1024>>>(bfc, out);
}